// round 3
// baseline (speedup 1.0000x reference)
#include <cuda_runtime.h>
#include <cstdint>

// ---------------------------------------------------------------------------
// Shifted window attention (Swin): B=32, H=W=64, C=256, heads=8, hd=32,
// window 8x8 (WS2=64), shift=4.
//
// 3 kernels:
//   k_qkv : qkv = gather(x) @ w_qkv^T + b_qkv   (roll+window gather fused)
//   k_attn: per (window, head) attention (bias + shift mask + softmax)
//   k_out : out = o @ w_out^T + b_out, scattered through inverse roll map
// All GEMMs: tf32 mma.sync m16n8k8, fp32 accumulate.
// ---------------------------------------------------------------------------

#define QKV_STRIDE 33554432   // 2048 windows * 8 heads * 64 tok * 32 dim
#define ASTRIDE    132        // smem row stride (128 + 4 pad): bank-clean frags
#define SCALE_F    0.1767766952966369f

// Scratch (device globals: no runtime allocation).
__device__ float g_qkv[100663296];  // 3 * QKV_STRIDE floats  (402 MB)
__device__ float g_o[33554432];     // 131072 x 256 floats    (134 MB)

__device__ __forceinline__ float tf32f(float f) {
    uint32_t u;
    asm("cvt.rna.tf32.f32 %0, %1;" : "=r"(u) : "f"(f));
    return __uint_as_float(u);
}

__device__ __forceinline__ void mma8(float* c,
                                     uint32_t a0, uint32_t a1, uint32_t a2, uint32_t a3,
                                     uint32_t b0, uint32_t b1) {
    asm volatile("mma.sync.aligned.m16n8k8.row.col.f32.tf32.tf32.f32 "
                 "{%0,%1,%2,%3},{%4,%5,%6,%7},{%8,%9},{%0,%1,%2,%3};\n"
                 : "+f"(c[0]), "+f"(c[1]), "+f"(c[2]), "+f"(c[3])
                 : "r"(a0), "r"(a1), "r"(a2), "r"(a3), "r"(b0), "r"(b1));
}

// Window-token index m (w*64+p) -> row in the original (B, 64, 64) image,
// accounting for the cyclic shift by 4 (same map for gather and scatter).
__device__ __forceinline__ int token_src(int m) {
    int w = m >> 6, p = m & 63;
    int b = w >> 6, widx = w & 63;
    int y = (((widx >> 3) << 3) + (p >> 3) + 4) & 63;
    int x = (((widx & 7) << 3) + (p & 7) + 4) & 63;
    return (b << 12) | (y << 6) | x;
}

// ---------------------------------------------------------------------------
// K1: QKV GEMM.  C[m, n] = sum_k A[m,k] * Wqkv[n,k] + b[n]
// CTA tile 128(M) x 64(N), K=256 in 2 chunks of 128. 8 warps of 32x32.
// Epilogue scatters to per-(which, window, head) layout for K2.
// ---------------------------------------------------------------------------
__global__ void __launch_bounds__(256, 2)
k_qkv(const float* __restrict__ x,
      const float* __restrict__ wqkv,
      const float* __restrict__ bqkv) {
    extern __shared__ float sm[];
    float* As = sm;                    // [128][132]
    float* Bs = sm + 128 * ASTRIDE;    // [64][132]

    const int t = threadIdx.x;
    const int mbase = blockIdx.y << 7;
    const int nbase = blockIdx.x << 6;
    const int lane = t & 31, wid = t >> 5;
    const int g = lane >> 2, tg = lane & 3;
    const int wm = (wid & 3) << 5;   // warp M offset: 0,32,64,96
    const int wn = (wid >> 2) << 5;  // warp N offset: 0,32

    // A loader: 2 threads per row, gather through the roll/window map.
    const int arow = t >> 1, apart = t & 1;
    const float* asrc = x + (size_t)token_src(mbase + arow) * 256 + apart * 64;
    float* adst = As + arow * ASTRIDE + apart * 64;
    // B loader: 4 threads per row.
    const int brow = t >> 2, bpart = t & 3;
    const float* bsrc = wqkv + (size_t)(nbase + brow) * 256 + bpart * 32;
    float* bdst = Bs + brow * ASTRIDE + bpart * 32;

    float acc[2][4][4];
#pragma unroll
    for (int i = 0; i < 2; ++i)
#pragma unroll
        for (int j = 0; j < 4; ++j)
#pragma unroll
            for (int k = 0; k < 4; ++k) acc[i][j][k] = 0.f;

    for (int kc = 0; kc < 2; ++kc) {
#pragma unroll
        for (int i = 0; i < 16; ++i) {
            float4 v = __ldg((const float4*)(asrc + kc * 128 + i * 4));
            float4 o;
            o.x = tf32f(v.x); o.y = tf32f(v.y); o.z = tf32f(v.z); o.w = tf32f(v.w);
            *(float4*)(adst + i * 4) = o;
        }
#pragma unroll
        for (int i = 0; i < 8; ++i) {
            float4 v = __ldg((const float4*)(bsrc + kc * 128 + i * 4));
            float4 o;
            o.x = tf32f(v.x); o.y = tf32f(v.y); o.z = tf32f(v.z); o.w = tf32f(v.w);
            *(float4*)(bdst + i * 4) = o;
        }
        __syncthreads();
#pragma unroll 4
        for (int k0 = 0; k0 < 128; k0 += 8) {
            uint32_t af[2][4];
#pragma unroll
            for (int mt = 0; mt < 2; ++mt) {
                const float* ap = As + (wm + mt * 16 + g) * ASTRIDE + k0 + tg;
                af[mt][0] = __float_as_uint(ap[0]);
                af[mt][1] = __float_as_uint(ap[8 * ASTRIDE]);
                af[mt][2] = __float_as_uint(ap[4]);
                af[mt][3] = __float_as_uint(ap[8 * ASTRIDE + 4]);
            }
            uint32_t bf[4][2];
#pragma unroll
            for (int nt = 0; nt < 4; ++nt) {
                const float* bp = Bs + (wn + nt * 8 + g) * ASTRIDE + k0 + tg;
                bf[nt][0] = __float_as_uint(bp[0]);
                bf[nt][1] = __float_as_uint(bp[4]);
            }
#pragma unroll
            for (int mt = 0; mt < 2; ++mt)
#pragma unroll
                for (int nt = 0; nt < 4; ++nt)
                    mma8(acc[mt][nt], af[mt][0], af[mt][1], af[mt][2], af[mt][3],
                         bf[nt][0], bf[nt][1]);
        }
        __syncthreads();
    }

    // Epilogue: +bias, scatter to g_qkv[which][w][h][p][d].
#pragma unroll
    for (int mt = 0; mt < 2; ++mt) {
#pragma unroll
        for (int half = 0; half < 2; ++half) {
            int m = mbase + wm + mt * 16 + g + half * 8;
            int w = m >> 6, p = m & 63;
#pragma unroll
            for (int nt = 0; nt < 4; ++nt) {
                int n0 = nbase + wn + nt * 8 + tg * 2;
                int which = n0 >> 8, h = (n0 >> 5) & 7, d = n0 & 31;
                float2 val;
                val.x = acc[mt][nt][half * 2 + 0] + __ldg(bqkv + n0);
                val.y = acc[mt][nt][half * 2 + 1] + __ldg(bqkv + n0 + 1);
                *(float2*)(g_qkv + (size_t)which * QKV_STRIDE
                           + ((size_t)(((w << 3) + h) << 6) + p) * 32 + d) = val;
            }
        }
    }
}

// ---------------------------------------------------------------------------
// K2: per-(window, head) attention. 1 CTA = 1 (w,h), 4 warps, each warp owns
// 16 full rows of S (all 64 cols) -> softmax entirely in-warp.
// ---------------------------------------------------------------------------
__global__ void __launch_bounds__(128)
k_attn(const float* __restrict__ pos_enc) {
    __shared__ float qs[64 * 36];
    __shared__ float ks[64 * 36];
    __shared__ float vs[64 * 36];
    __shared__ float ps[64 * 68];
    __shared__ float pos_s[225];

    const int t = threadIdx.x;
    const int bh = blockIdx.x;
    const int w = bh >> 3, h = bh & 7;
    const int base = ((w << 3) + h) << 11;  // *2048 floats

    // Load q,k,v tiles (64x32 each) with tf32 rounding at store.
#pragma unroll
    for (int i = 0; i < 4; ++i) {
        int t4 = t + (i << 7);               // 0..511 float4s
        int row = t4 >> 3, col = (t4 & 7) << 2;
        int off = row * 36 + col;
        float4 v = __ldg((const float4*)(g_qkv + base + (t4 << 2)));
        qs[off] = tf32f(v.x); qs[off + 1] = tf32f(v.y);
        qs[off + 2] = tf32f(v.z); qs[off + 3] = tf32f(v.w);
        v = __ldg((const float4*)(g_qkv + QKV_STRIDE + base + (t4 << 2)));
        ks[off] = tf32f(v.x); ks[off + 1] = tf32f(v.y);
        ks[off + 2] = tf32f(v.z); ks[off + 3] = tf32f(v.w);
        v = __ldg((const float4*)(g_qkv + 2 * QKV_STRIDE + base + (t4 << 2)));
        vs[off] = tf32f(v.x); vs[off + 1] = tf32f(v.y);
        vs[off + 2] = tf32f(v.z); vs[off + 3] = tf32f(v.w);
    }
    for (int i = t; i < 225; i += 128) pos_s[i] = __ldg(pos_enc + h * 225 + i);
    __syncthreads();

    const int lane = t & 31, wid = t >> 5;
    const int g = lane >> 2, tg = lane & 3;
    const int wb = wid << 4;  // warp row base (16 rows per warp)

    // S = q k^T
    float sacc[8][4];
#pragma unroll
    for (int nt = 0; nt < 8; ++nt)
#pragma unroll
        for (int k = 0; k < 4; ++k) sacc[nt][k] = 0.f;

#pragma unroll
    for (int k0 = 0; k0 < 32; k0 += 8) {
        const float* ap = qs + (wb + g) * 36 + k0 + tg;
        uint32_t a0 = __float_as_uint(ap[0]);
        uint32_t a1 = __float_as_uint(ap[8 * 36]);
        uint32_t a2 = __float_as_uint(ap[4]);
        uint32_t a3 = __float_as_uint(ap[8 * 36 + 4]);
#pragma unroll
        for (int nt = 0; nt < 8; ++nt) {
            const float* bp = ks + ((nt << 3) + g) * 36 + k0 + tg;
            mma8(sacc[nt], a0, a1, a2, a3,
                 __float_as_uint(bp[0]), __float_as_uint(bp[4]));
        }
    }

    // scale + relative position bias + shift mask
    const int widx = w & 63;
    const int my = ((widx >> 3) == 7);
    const int mxw = ((widx & 7) == 7);
    auto regf = [&](int py, int px) {
        int ry = my ? (py < 4 ? 1 : 2) : 0;
        int rx = mxw ? (px < 4 ? 1 : 2) : 0;
        return ry * 3 + rx;
    };
    const int iL = wb + g, iH = iL + 8;
    const int pyL = iL >> 3, pxL = iL & 7;
    const int pyH = iH >> 3, pxH = iH & 7;
    const int regL = regf(pyL, pxL), regH = regf(pyH, pxH);

    float mL = -1e30f, mH = -1e30f;
#pragma unroll
    for (int nt = 0; nt < 8; ++nt) {
#pragma unroll
        for (int jj = 0; jj < 2; ++jj) {
            int j = (nt << 3) + (tg << 1) + jj;
            int pyj = j >> 3, pxj = j & 7;
            int regj = regf(pyj, pxj);
            float sL = sacc[nt][jj] * SCALE_F
                       + pos_s[(pyL - pyj + 7) * 15 + (pxL - pxj + 7)];
            float sH = sacc[nt][2 + jj] * SCALE_F
                       + pos_s[(pyH - pyj + 7) * 15 + (pxH - pxj + 7)];
            if (regj != regL) sL = -1e30f;
            if (regj != regH) sH = -1e30f;
            sacc[nt][jj] = sL;
            sacc[nt][2 + jj] = sH;
            mL = fmaxf(mL, sL);
            mH = fmaxf(mH, sH);
        }
    }
    mL = fmaxf(mL, __shfl_xor_sync(0xffffffffu, mL, 1));
    mL = fmaxf(mL, __shfl_xor_sync(0xffffffffu, mL, 2));
    mH = fmaxf(mH, __shfl_xor_sync(0xffffffffu, mH, 1));
    mH = fmaxf(mH, __shfl_xor_sync(0xffffffffu, mH, 2));

    float sumL = 0.f, sumH = 0.f;
#pragma unroll
    for (int nt = 0; nt < 8; ++nt) {
#pragma unroll
        for (int jj = 0; jj < 2; ++jj) {
            int j = (nt << 3) + (tg << 1) + jj;
            float eL = tf32f(__expf(sacc[nt][jj] - mL));
            float eH = tf32f(__expf(sacc[nt][2 + jj] - mH));
            sumL += eL;
            sumH += eH;
            ps[iL * 68 + j] = eL;
            ps[iH * 68 + j] = eH;
        }
    }
    sumL += __shfl_xor_sync(0xffffffffu, sumL, 1);
    sumL += __shfl_xor_sync(0xffffffffu, sumL, 2);
    sumH += __shfl_xor_sync(0xffffffffu, sumH, 1);
    sumH += __shfl_xor_sync(0xffffffffu, sumH, 2);
    const float invL = 1.f / sumL, invH = 1.f / sumH;
    __syncwarp();

    // O = P V  (16x64 x 64x32 per warp)
    float oacc[4][4];
#pragma unroll
    for (int nt = 0; nt < 4; ++nt)
#pragma unroll
        for (int k = 0; k < 4; ++k) oacc[nt][k] = 0.f;

#pragma unroll
    for (int kk = 0; kk < 64; kk += 8) {
        const float* ap = ps + (wb + g) * 68 + kk + tg;
        uint32_t a0 = __float_as_uint(ap[0]);
        uint32_t a1 = __float_as_uint(ap[8 * 68]);
        uint32_t a2 = __float_as_uint(ap[4]);
        uint32_t a3 = __float_as_uint(ap[8 * 68 + 4]);
#pragma unroll
        for (int nt = 0; nt < 4; ++nt) {
            const float* bp = vs + (kk + tg) * 36 + (nt << 3) + g;
            mma8(oacc[nt], a0, a1, a2, a3,
                 __float_as_uint(bp[0]), __float_as_uint(bp[4 * 36]));
        }
    }

    float* ob = g_o + (size_t)(w << 6) * 256 + (h << 5);
#pragma unroll
    for (int nt = 0; nt < 4; ++nt) {
        int d = (nt << 3) + (tg << 1);
        float2 vL = make_float2(oacc[nt][0] * invL, oacc[nt][1] * invL);
        float2 vH = make_float2(oacc[nt][2] * invH, oacc[nt][3] * invH);
        *(float2*)(ob + (size_t)iL * 256 + d) = vL;
        *(float2*)(ob + (size_t)iH * 256 + d) = vH;
    }
}

// ---------------------------------------------------------------------------
// K3: out = o @ w_out^T + b_out, scatter through inverse-roll token map.
// Same tiling as K1; A rows are contiguous (no gather).
// ---------------------------------------------------------------------------
__global__ void __launch_bounds__(256, 2)
k_out(const float* __restrict__ wout,
      const float* __restrict__ bout,
      float* __restrict__ out) {
    extern __shared__ float sm[];
    float* As = sm;
    float* Bs = sm + 128 * ASTRIDE;

    const int t = threadIdx.x;
    const int mbase = blockIdx.y << 7;
    const int nbase = blockIdx.x << 6;
    const int lane = t & 31, wid = t >> 5;
    const int g = lane >> 2, tg = lane & 3;
    const int wm = (wid & 3) << 5;
    const int wn = (wid >> 2) << 5;

    const int arow = t >> 1, apart = t & 1;
    const float* asrc = g_o + (size_t)(mbase + arow) * 256 + apart * 64;
    float* adst = As + arow * ASTRIDE + apart * 64;
    const int brow = t >> 2, bpart = t & 3;
    const float* bsrc = wout + (size_t)(nbase + brow) * 256 + bpart * 32;
    float* bdst = Bs + brow * ASTRIDE + bpart * 32;

    float acc[2][4][4];
#pragma unroll
    for (int i = 0; i < 2; ++i)
#pragma unroll
        for (int j = 0; j < 4; ++j)
#pragma unroll
            for (int k = 0; k < 4; ++k) acc[i][j][k] = 0.f;

    for (int kc = 0; kc < 2; ++kc) {
#pragma unroll
        for (int i = 0; i < 16; ++i) {
            float4 v = __ldg((const float4*)(asrc + kc * 128 + i * 4));
            float4 o;
            o.x = tf32f(v.x); o.y = tf32f(v.y); o.z = tf32f(v.z); o.w = tf32f(v.w);
            *(float4*)(adst + i * 4) = o;
        }
#pragma unroll
        for (int i = 0; i < 8; ++i) {
            float4 v = __ldg((const float4*)(bsrc + kc * 128 + i * 4));
            float4 o;
            o.x = tf32f(v.x); o.y = tf32f(v.y); o.z = tf32f(v.z); o.w = tf32f(v.w);
            *(float4*)(bdst + i * 4) = o;
        }
        __syncthreads();
#pragma unroll 4
        for (int k0 = 0; k0 < 128; k0 += 8) {
            uint32_t af[2][4];
#pragma unroll
            for (int mt = 0; mt < 2; ++mt) {
                const float* ap = As + (wm + mt * 16 + g) * ASTRIDE + k0 + tg;
                af[mt][0] = __float_as_uint(ap[0]);
                af[mt][1] = __float_as_uint(ap[8 * ASTRIDE]);
                af[mt][2] = __float_as_uint(ap[4]);
                af[mt][3] = __float_as_uint(ap[8 * ASTRIDE + 4]);
            }
            uint32_t bf[4][2];
#pragma unroll
            for (int nt = 0; nt < 4; ++nt) {
                const float* bp = Bs + (wn + nt * 8 + g) * ASTRIDE + k0 + tg;
                bf[nt][0] = __float_as_uint(bp[0]);
                bf[nt][1] = __float_as_uint(bp[4]);
            }
#pragma unroll
            for (int mt = 0; mt < 2; ++mt)
#pragma unroll
                for (int nt = 0; nt < 4; ++nt)
                    mma8(acc[mt][nt], af[mt][0], af[mt][1], af[mt][2], af[mt][3],
                         bf[nt][0], bf[nt][1]);
        }
        __syncthreads();
    }

#pragma unroll
    for (int mt = 0; mt < 2; ++mt) {
#pragma unroll
        for (int half = 0; half < 2; ++half) {
            int m = mbase + wm + mt * 16 + g + half * 8;
            float* dst = out + (size_t)token_src(m) * 256;
#pragma unroll
            for (int nt = 0; nt < 4; ++nt) {
                int n0 = nbase + wn + nt * 8 + tg * 2;
                float2 val;
                val.x = acc[mt][nt][half * 2 + 0] + __ldg(bout + n0);
                val.y = acc[mt][nt][half * 2 + 1] + __ldg(bout + n0 + 1);
                *(float2*)(dst + n0) = val;
            }
        }
    }
}

// ---------------------------------------------------------------------------
extern "C" void kernel_launch(void* const* d_in, const int* in_sizes, int n_in,
                              void* d_out, int out_size) {
    const float* x    = (const float*)d_in[0];  // 32*4096*256
    const float* wqkv = (const float*)d_in[1];  // 768*256
    const float* bqkv = (const float*)d_in[2];  // 768
    const float* wout = (const float*)d_in[3];  // 256*256
    const float* bout = (const float*)d_in[4];  // 256
    const float* pos  = (const float*)d_in[5];  // 8*225
    float* out = (float*)d_out;

    const int smem = (128 + 64) * ASTRIDE * sizeof(float);  // 101376 B
    cudaFuncSetAttribute(k_qkv, cudaFuncAttributeMaxDynamicSharedMemorySize, smem);
    cudaFuncSetAttribute(k_out, cudaFuncAttributeMaxDynamicSharedMemorySize, smem);

    k_qkv<<<dim3(12, 1024), 256, smem>>>(x, wqkv, bqkv);
    k_attn<<<16384, 128>>>(pos);
    k_out<<<dim3(4, 1024), 256, smem>>>(wout, bout, out);
}

// round 4
// speedup vs baseline: 2.1498x; 2.1498x over previous
#include <cuda_runtime.h>
#include <cstdint>

// ---------------------------------------------------------------------------
// Swin shifted-window attention. B=32, 64x64, C=256, 8 heads x 32, ws=8, shift=4.
// k_round: pre-round x, w_qkv, w_out to tf32 (RNA) for cp.async mainloops.
// k_qkv  : qkv = gather(x) @ w_qkv^T + b  (cp.async + ldmatrix + mma tf32)
// k_attn : per (window,head) attention, bias+mask+softmax, writes rounded o
// k_out  : out = o @ w_out^T + b, scatter through inverse roll map
// ---------------------------------------------------------------------------

#define SCALE_F 0.1767766952966369f
#define ABYTES   18432              // 128*36*4
#define BUFBYTES 36864              // A+B one stage

__device__ float g_xr[33554432];    // rounded x
__device__ float g_wqkv[196608];    // rounded w_qkv
__device__ float g_wout[65536];     // rounded w_out
__device__ float g_q[33554432];     // [win][head][tok 64][d 32]
__device__ float g_k[33554432];     // [win][head][tok 64][d 32]
__device__ float g_v[33554432];     // [win][head][d 32][tok 64]  (transposed)
__device__ float g_o[33554432];     // [token 131072][256] rounded

__device__ __forceinline__ float tf32f(float f) {
    uint32_t u;
    asm("cvt.rna.tf32.f32 %0, %1;" : "=r"(u) : "f"(f));
    return __uint_as_float(u);
}
__device__ __forceinline__ uint32_t smem_u32(const void* p) {
    return (uint32_t)__cvta_generic_to_shared(p);
}
__device__ __forceinline__ void cp16(uint32_t s, const void* g) {
    asm volatile("cp.async.cg.shared.global [%0], [%1], 16;" :: "r"(s), "l"(g));
}
__device__ __forceinline__ void cp_commit() {
    asm volatile("cp.async.commit_group;");
}
template <int N> __device__ __forceinline__ void cp_wait() {
    asm volatile("cp.async.wait_group %0;" :: "n"(N));
}
__device__ __forceinline__ void ldsm4(uint32_t* r, uint32_t a) {
    asm volatile("ldmatrix.sync.aligned.m8n8.x4.shared.b16 {%0,%1,%2,%3}, [%4];"
                 : "=r"(r[0]), "=r"(r[1]), "=r"(r[2]), "=r"(r[3]) : "r"(a));
}
__device__ __forceinline__ void mma8(float* c, const uint32_t* a,
                                     uint32_t b0, uint32_t b1) {
    asm volatile("mma.sync.aligned.m16n8k8.row.col.f32.tf32.tf32.f32 "
                 "{%0,%1,%2,%3},{%4,%5,%6,%7},{%8,%9},{%0,%1,%2,%3};\n"
                 : "+f"(c[0]), "+f"(c[1]), "+f"(c[2]), "+f"(c[3])
                 : "r"(a[0]), "r"(a[1]), "r"(a[2]), "r"(a[3]), "r"(b0), "r"(b1));
}

// window-token m -> source row in (B,64,64), cyclic shift by 4 (self-inverse map)
__device__ __forceinline__ int token_src(int m) {
    int w = m >> 6, p = m & 63;
    int b = w >> 6, widx = w & 63;
    int y = (((widx >> 3) << 3) + (p >> 3) + 4) & 63;
    int x = (((widx & 7) << 3) + (p & 7) + 4) & 63;
    return (b << 12) | (y << 6) | x;
}

// ---------------------------------------------------------------------------
__global__ void k_round(const float* __restrict__ x,
                        const float* __restrict__ wq,
                        const float* __restrict__ wo) {
    const long NX = 33554432 / 4, NQ = 196608 / 4, NO = 65536 / 4;
    long stride = (long)gridDim.x * blockDim.x;
    for (long i = (long)blockIdx.x * blockDim.x + threadIdx.x; i < NX + NQ + NO;
         i += stride) {
        const float4* s;
        float4* d;
        if (i < NX)          { s = (const float4*)x  + i;           d = (float4*)g_xr   + i; }
        else if (i < NX + NQ){ s = (const float4*)wq + (i - NX);    d = (float4*)g_wqkv + (i - NX); }
        else                 { s = (const float4*)wo + (i - NX - NQ); d = (float4*)g_wout + (i - NX - NQ); }
        float4 v = __ldg(s);
        v.x = tf32f(v.x); v.y = tf32f(v.y); v.z = tf32f(v.z); v.w = tf32f(v.w);
        *d = v;
    }
}

// ---------------------------------------------------------------------------
// K1: qkv GEMM. CTA 128(M) x 128(N), K=256 in 8 chunks of 32, double buffered.
// 8 warps: 2(M,64) x 4(N,32). Epilogue scatters rounded q/k/v.
// ---------------------------------------------------------------------------
__global__ void __launch_bounds__(256, 2)
k_qkv(const float* __restrict__ bqkv) {
    extern __shared__ float smf[];
    const int t = threadIdx.x;
    const int mbase = blockIdx.y << 7;
    const int nbase = blockIdx.x << 7;
    const int lane = t & 31, wid = t >> 5;
    const int g = lane >> 2, tg = lane & 3;
    const int wm = (wid & 1) << 6;
    const int wn = (wid >> 1) << 5;

    const uint32_t sbase = smem_u32(smf);
    const int srow = t >> 1, scol = (t & 1) << 4;
    const float* gA = g_xr + (size_t)token_src(mbase + srow) * 256 + scol;
    const float* gB = g_wqkv + (size_t)(nbase + srow) * 256 + scol;
    const uint32_t sA = sbase + (srow * 36 + scol) * 4;
    const uint32_t sB = sA + ABYTES;

    const int tt = lane >> 3, rr = lane & 7;
    const uint32_t aoff = (((tt & 1) * 8 + rr) * 36 + (tt >> 1) * 4) * 4;
    const uint32_t boff = (((tt >> 1) * 8 + rr) * 36 + (tt & 1) * 4) * 4;

    float acc[4][4][4] = {};

    // prologue: stage chunk 0 into buf 0
    {
        const float* pa = gA;
        const float* pb = gB;
#pragma unroll
        for (int j = 0; j < 4; ++j) { cp16(sA + j * 16, pa + j * 4); }
#pragma unroll
        for (int j = 0; j < 4; ++j) { cp16(sB + j * 16, pb + j * 4); }
        cp_commit();
    }

    for (int kc = 0; kc < 8; ++kc) {
        if (kc < 7) {
            uint32_t bo = ((kc + 1) & 1) * BUFBYTES;
            const float* pa = gA + (kc + 1) * 32;
            const float* pb = gB + (kc + 1) * 32;
#pragma unroll
            for (int j = 0; j < 4; ++j) { cp16(sA + bo + j * 16, pa + j * 4); }
#pragma unroll
            for (int j = 0; j < 4; ++j) { cp16(sB + bo + j * 16, pb + j * 4); }
            cp_commit();
            cp_wait<1>();
        } else {
            cp_wait<0>();
        }
        __syncthreads();

        const uint32_t base = sbase + (kc & 1) * BUFBYTES;
#pragma unroll
        for (int k8 = 0; k8 < 4; ++k8) {
            uint32_t af[4][4];
#pragma unroll
            for (int mt = 0; mt < 4; ++mt)
                ldsm4(af[mt], base + (wm + mt * 16) * 144 + aoff + k8 * 32);
            uint32_t bf[2][4];
#pragma unroll
            for (int bt = 0; bt < 2; ++bt)
                ldsm4(bf[bt], base + ABYTES + (wn + bt * 16) * 144 + boff + k8 * 32);
#pragma unroll
            for (int mt = 0; mt < 4; ++mt) {
                mma8(acc[mt][0], af[mt], bf[0][0], bf[0][1]);
                mma8(acc[mt][1], af[mt], bf[0][2], bf[0][3]);
                mma8(acc[mt][2], af[mt], bf[1][0], bf[1][1]);
                mma8(acc[mt][3], af[mt], bf[1][2], bf[1][3]);
            }
        }
        __syncthreads();
    }

    const int which = nbase >> 8;  // uniform per CTA: 0=q, 1=k, 2=v
#pragma unroll
    for (int mt = 0; mt < 4; ++mt) {
#pragma unroll
        for (int half = 0; half < 2; ++half) {
            int m = mbase + wm + mt * 16 + g + half * 8;
            int w = m >> 6, p = m & 63;
#pragma unroll
            for (int nt = 0; nt < 4; ++nt) {
                int n0 = nbase + wn + nt * 8 + tg * 2;
                int h = (n0 >> 5) & 7, d = n0 & 31;
                int wh = (w << 3) + h;
                float v0 = tf32f(acc[mt][nt][half * 2 + 0] + __ldg(bqkv + n0));
                float v1 = tf32f(acc[mt][nt][half * 2 + 1] + __ldg(bqkv + n0 + 1));
                if (which == 0) {
                    *(float2*)(g_q + ((wh << 6) + p) * 32 + d) = make_float2(v0, v1);
                } else if (which == 1) {
                    *(float2*)(g_k + ((wh << 6) + p) * 32 + d) = make_float2(v0, v1);
                } else {
                    g_v[(((wh << 5) + d) << 6) + p] = v0;
                    g_v[(((wh << 5) + d + 1) << 6) + p] = v1;
                }
            }
        }
    }
}

// ---------------------------------------------------------------------------
// K2: attention per (window, head). 4 warps, each owns 16 full S rows.
// ---------------------------------------------------------------------------
__global__ void __launch_bounds__(128)
k_attn(const float* __restrict__ pos_enc) {
    __shared__ float qs[64 * 36];
    __shared__ float ks[64 * 36];
    __shared__ float vs[32 * 68];
    __shared__ float ps[64 * 68];
    __shared__ float pos_s[232];

    const int t = threadIdx.x;
    const int bh = blockIdx.x;
    const int w = bh >> 3, h = bh & 7;
    const int wh = (w << 3) + h;

    // staging: q,k (64x32), v (32x64, pre-transposed) via cp.async
    {
        int row = t >> 1, col = (t & 1) << 4;
        const float* q = g_q + ((size_t)(wh << 6) + row) * 32 + col;
        const float* k = g_k + ((size_t)(wh << 6) + row) * 32 + col;
        uint32_t dq = smem_u32(qs) + (row * 36 + col) * 4;
        uint32_t dk = smem_u32(ks) + (row * 36 + col) * 4;
#pragma unroll
        for (int j = 0; j < 4; ++j) { cp16(dq + j * 16, q + j * 4); cp16(dk + j * 16, k + j * 4); }
        int vr = t >> 2, vc = (t & 3) << 4;
        const float* v = g_v + ((size_t)(wh << 5) + vr) * 64 + vc;
        uint32_t dv = smem_u32(vs) + (vr * 68 + vc) * 4;
#pragma unroll
        for (int j = 0; j < 4; ++j) { cp16(dv + j * 16, v + j * 4); }
        cp_commit();
    }
    for (int i = t; i < 225; i += 128) pos_s[i] = __ldg(pos_enc + h * 225 + i);
    cp_wait<0>();
    __syncthreads();

    const int lane = t & 31, wid = t >> 5;
    const int g = lane >> 2, tg = lane & 3;
    const int wb = wid << 4;
    const int tt = lane >> 3, rr = lane & 7;
    const uint32_t aoff36 = (((tt & 1) * 8 + rr) * 36 + (tt >> 1) * 4) * 4;
    const uint32_t boff36 = (((tt >> 1) * 8 + rr) * 36 + (tt & 1) * 4) * 4;
    const uint32_t aoff68 = (((tt & 1) * 8 + rr) * 68 + (tt >> 1) * 4) * 4;
    const uint32_t boff68 = (((tt >> 1) * 8 + rr) * 68 + (tt & 1) * 4) * 4;

    // S = q k^T
    float sacc[8][4] = {};
    const uint32_t qb = smem_u32(qs) + wb * 144 + aoff36;
    const uint32_t kb = smem_u32(ks) + boff36;
#pragma unroll
    for (int k8 = 0; k8 < 4; ++k8) {
        uint32_t af[4];
        ldsm4(af, qb + k8 * 32);
        uint32_t bf[4][4];
#pragma unroll
        for (int bt = 0; bt < 4; ++bt)
            ldsm4(bf[bt], kb + bt * 16 * 144 + k8 * 32);
#pragma unroll
        for (int nt = 0; nt < 8; ++nt)
            mma8(sacc[nt], af, bf[nt >> 1][(nt & 1) * 2], bf[nt >> 1][(nt & 1) * 2 + 1]);
    }

    // bias + shift mask + softmax (rows iL, iH owned fully by this quarter-warp)
    const int widx = w & 63;
    const int my = ((widx >> 3) == 7);
    const int mxw = ((widx & 7) == 7);
    auto regf = [&](int py, int px) {
        int ry = my ? (py < 4 ? 1 : 2) : 0;
        int rx = mxw ? (px < 4 ? 1 : 2) : 0;
        return ry * 3 + rx;
    };
    const int iL = wb + g, iH = iL + 8;
    const int pyL = iL >> 3, pxL = iL & 7;
    const int pyH = iH >> 3, pxH = iH & 7;
    const int regL = regf(pyL, pxL), regH = regf(pyH, pxH);

    float mL = -1e30f, mH = -1e30f;
#pragma unroll
    for (int nt = 0; nt < 8; ++nt) {
#pragma unroll
        for (int jj = 0; jj < 2; ++jj) {
            int j = (nt << 3) + (tg << 1) + jj;
            int pyj = j >> 3, pxj = j & 7;
            int regj = regf(pyj, pxj);
            float sL = sacc[nt][jj] * SCALE_F + pos_s[(pyL - pyj + 7) * 15 + (pxL - pxj + 7)];
            float sH = sacc[nt][2 + jj] * SCALE_F + pos_s[(pyH - pyj + 7) * 15 + (pxH - pxj + 7)];
            if (regj != regL) sL = -1e30f;
            if (regj != regH) sH = -1e30f;
            sacc[nt][jj] = sL;
            sacc[nt][2 + jj] = sH;
            mL = fmaxf(mL, sL);
            mH = fmaxf(mH, sH);
        }
    }
    mL = fmaxf(mL, __shfl_xor_sync(0xffffffffu, mL, 1));
    mL = fmaxf(mL, __shfl_xor_sync(0xffffffffu, mL, 2));
    mH = fmaxf(mH, __shfl_xor_sync(0xffffffffu, mH, 1));
    mH = fmaxf(mH, __shfl_xor_sync(0xffffffffu, mH, 2));

    float sumL = 0.f, sumH = 0.f;
#pragma unroll
    for (int nt = 0; nt < 8; ++nt) {
#pragma unroll
        for (int jj = 0; jj < 2; ++jj) {
            int j = (nt << 3) + (tg << 1) + jj;
            float eL = tf32f(__expf(sacc[nt][jj] - mL));
            float eH = tf32f(__expf(sacc[nt][2 + jj] - mH));
            sumL += eL;
            sumH += eH;
            ps[iL * 68 + j] = eL;
            ps[iH * 68 + j] = eH;
        }
    }
    sumL += __shfl_xor_sync(0xffffffffu, sumL, 1);
    sumL += __shfl_xor_sync(0xffffffffu, sumL, 2);
    sumH += __shfl_xor_sync(0xffffffffu, sumH, 1);
    sumH += __shfl_xor_sync(0xffffffffu, sumH, 2);
    const float invL = 1.f / sumL, invH = 1.f / sumH;
    __syncwarp();

    // O = P V
    float oacc[4][4] = {};
    const uint32_t pb = smem_u32(ps) + wb * 272 + aoff68;
    const uint32_t vb = smem_u32(vs) + boff68;
#pragma unroll
    for (int k8 = 0; k8 < 8; ++k8) {
        uint32_t pf[4];
        ldsm4(pf, pb + k8 * 32);
        uint32_t vf[2][4];
#pragma unroll
        for (int bt = 0; bt < 2; ++bt)
            ldsm4(vf[bt], vb + bt * 16 * 272 + k8 * 32);
#pragma unroll
        for (int nt = 0; nt < 4; ++nt)
            mma8(oacc[nt], pf, vf[nt >> 1][(nt & 1) * 2], vf[nt >> 1][(nt & 1) * 2 + 1]);
    }

    float* ob = g_o + (size_t)(w << 6) * 256 + (h << 5);
#pragma unroll
    for (int nt = 0; nt < 4; ++nt) {
        int d = (nt << 3) + (tg << 1);
        *(float2*)(ob + (size_t)iL * 256 + d) =
            make_float2(tf32f(oacc[nt][0] * invL), tf32f(oacc[nt][1] * invL));
        *(float2*)(ob + (size_t)iH * 256 + d) =
            make_float2(tf32f(oacc[nt][2] * invH), tf32f(oacc[nt][3] * invH));
    }
}

// ---------------------------------------------------------------------------
// K3: out = o @ w_out^T + b_out, scatter through inverse roll map.
// ---------------------------------------------------------------------------
__global__ void __launch_bounds__(256, 2)
k_out(const float* __restrict__ bout, float* __restrict__ out) {
    extern __shared__ float smf[];
    const int t = threadIdx.x;
    const int mbase = blockIdx.y << 7;
    const int nbase = blockIdx.x << 7;
    const int lane = t & 31, wid = t >> 5;
    const int g = lane >> 2, tg = lane & 3;
    const int wm = (wid & 1) << 6;
    const int wn = (wid >> 1) << 5;

    const uint32_t sbase = smem_u32(smf);
    const int srow = t >> 1, scol = (t & 1) << 4;
    const float* gA = g_o + (size_t)(mbase + srow) * 256 + scol;
    const float* gB = g_wout + (size_t)(nbase + srow) * 256 + scol;
    const uint32_t sA = sbase + (srow * 36 + scol) * 4;
    const uint32_t sB = sA + ABYTES;

    const int tt = lane >> 3, rr = lane & 7;
    const uint32_t aoff = (((tt & 1) * 8 + rr) * 36 + (tt >> 1) * 4) * 4;
    const uint32_t boff = (((tt >> 1) * 8 + rr) * 36 + (tt & 1) * 4) * 4;

    float acc[4][4][4] = {};

    {
#pragma unroll
        for (int j = 0; j < 4; ++j) { cp16(sA + j * 16, gA + j * 4); }
#pragma unroll
        for (int j = 0; j < 4; ++j) { cp16(sB + j * 16, gB + j * 4); }
        cp_commit();
    }

    for (int kc = 0; kc < 8; ++kc) {
        if (kc < 7) {
            uint32_t bo = ((kc + 1) & 1) * BUFBYTES;
            const float* pa = gA + (kc + 1) * 32;
            const float* pb = gB + (kc + 1) * 32;
#pragma unroll
            for (int j = 0; j < 4; ++j) { cp16(sA + bo + j * 16, pa + j * 4); }
#pragma unroll
            for (int j = 0; j < 4; ++j) { cp16(sB + bo + j * 16, pb + j * 4); }
            cp_commit();
            cp_wait<1>();
        } else {
            cp_wait<0>();
        }
        __syncthreads();

        const uint32_t base = sbase + (kc & 1) * BUFBYTES;
#pragma unroll
        for (int k8 = 0; k8 < 4; ++k8) {
            uint32_t af[4][4];
#pragma unroll
            for (int mt = 0; mt < 4; ++mt)
                ldsm4(af[mt], base + (wm + mt * 16) * 144 + aoff + k8 * 32);
            uint32_t bf[2][4];
#pragma unroll
            for (int bt = 0; bt < 2; ++bt)
                ldsm4(bf[bt], base + ABYTES + (wn + bt * 16) * 144 + boff + k8 * 32);
#pragma unroll
            for (int mt = 0; mt < 4; ++mt) {
                mma8(acc[mt][0], af[mt], bf[0][0], bf[0][1]);
                mma8(acc[mt][1], af[mt], bf[0][2], bf[0][3]);
                mma8(acc[mt][2], af[mt], bf[1][0], bf[1][1]);
                mma8(acc[mt][3], af[mt], bf[1][2], bf[1][3]);
            }
        }
        __syncthreads();
    }

#pragma unroll
    for (int mt = 0; mt < 4; ++mt) {
#pragma unroll
        for (int half = 0; half < 2; ++half) {
            int m = mbase + wm + mt * 16 + g + half * 8;
            float* dst = out + (size_t)token_src(m) * 256;
#pragma unroll
            for (int nt = 0; nt < 4; ++nt) {
                int n0 = nbase + wn + nt * 8 + tg * 2;
                float2 val;
                val.x = acc[mt][nt][half * 2 + 0] + __ldg(bout + n0);
                val.y = acc[mt][nt][half * 2 + 1] + __ldg(bout + n0 + 1);
                *(float2*)(dst + n0) = val;
            }
        }
    }
}

// ---------------------------------------------------------------------------
extern "C" void kernel_launch(void* const* d_in, const int* in_sizes, int n_in,
                              void* d_out, int out_size) {
    const float* x    = (const float*)d_in[0];
    const float* wqkv = (const float*)d_in[1];
    const float* bqkv = (const float*)d_in[2];
    const float* wout = (const float*)d_in[3];
    const float* bout = (const float*)d_in[4];
    const float* pos  = (const float*)d_in[5];
    float* out = (float*)d_out;

    const int smem = 2 * BUFBYTES;  // 73728
    cudaFuncSetAttribute(k_qkv, cudaFuncAttributeMaxDynamicSharedMemorySize, smem);
    cudaFuncSetAttribute(k_out, cudaFuncAttributeMaxDynamicSharedMemorySize, smem);

    k_round<<<8192, 256>>>(x, wqkv, wout);
    k_qkv<<<dim3(6, 1024), 256, smem>>>(bqkv);
    k_attn<<<16384, 128>>>(pos);
    k_out<<<dim3(2, 1024), 256, smem>>>(bout, out);
}

// round 5
// speedup vs baseline: 2.3638x; 1.0995x over previous
#include <cuda_runtime.h>
#include <cstdint>

// ---------------------------------------------------------------------------
// Swin shifted-window attention. B=32, 64x64, C=256, 8 heads x 32, ws=8, shift=4.
// k_round: pre-round w_qkv, w_out to tf32 (RNA)          (~1 MB, ~5 us)
// k_qkv  : qkv = gather(x) @ w_qkv^T + b ; A staged LDG+cvt+STS, B cp.async,
//          3-stage ring, 1 sync per K-chunk, ldmatrix + mma tf32
// k_attn : per (window,head) attention, bias+mask+softmax, writes rounded o
// k_out  : out = o @ w_out^T + b, 3-stage cp.async ring, inverse-roll scatter
// ---------------------------------------------------------------------------

#define SCALE_F 0.1767766952966369f
#define ABYTES  18432               // 128*36*4 (one operand, one stage)
#define STAGE   36864               // A+B one stage

__device__ float g_wqkv[196608];    // rounded w_qkv
__device__ float g_wout[65536];     // rounded w_out
__device__ float g_q[33554432];     // [win][head][tok 64][d 32]
__device__ float g_k[33554432];     // [win][head][tok 64][d 32]
__device__ float g_v[33554432];     // [win][head][d 32][tok 64]  (transposed)
__device__ float g_o[33554432];     // [token 131072][256] rounded

__device__ __forceinline__ float tf32f(float f) {
    uint32_t u;
    asm("cvt.rna.tf32.f32 %0, %1;" : "=r"(u) : "f"(f));
    return __uint_as_float(u);
}
__device__ __forceinline__ uint32_t smem_u32(const void* p) {
    return (uint32_t)__cvta_generic_to_shared(p);
}
__device__ __forceinline__ void cp16(uint32_t s, const void* g) {
    asm volatile("cp.async.cg.shared.global [%0], [%1], 16;" :: "r"(s), "l"(g));
}
__device__ __forceinline__ void cp_commit() {
    asm volatile("cp.async.commit_group;");
}
template <int N> __device__ __forceinline__ void cp_wait() {
    asm volatile("cp.async.wait_group %0;" :: "n"(N));
}
__device__ __forceinline__ void ldsm4(uint32_t* r, uint32_t a) {
    asm volatile("ldmatrix.sync.aligned.m8n8.x4.shared.b16 {%0,%1,%2,%3}, [%4];"
                 : "=r"(r[0]), "=r"(r[1]), "=r"(r[2]), "=r"(r[3]) : "r"(a));
}
__device__ __forceinline__ void mma8(float* c, const uint32_t* a,
                                     uint32_t b0, uint32_t b1) {
    asm volatile("mma.sync.aligned.m16n8k8.row.col.f32.tf32.tf32.f32 "
                 "{%0,%1,%2,%3},{%4,%5,%6,%7},{%8,%9},{%0,%1,%2,%3};\n"
                 : "+f"(c[0]), "+f"(c[1]), "+f"(c[2]), "+f"(c[3])
                 : "r"(a[0]), "r"(a[1]), "r"(a[2]), "r"(a[3]), "r"(b0), "r"(b1));
}

// window-token m -> source row in (B,64,64), cyclic shift by 4 (self-inverse map)
__device__ __forceinline__ int token_src(int m) {
    int w = m >> 6, p = m & 63;
    int b = w >> 6, widx = w & 63;
    int y = (((widx >> 3) << 3) + (p >> 3) + 4) & 63;
    int x = (((widx & 7) << 3) + (p & 7) + 4) & 63;
    return (b << 12) | (y << 6) | x;
}

// ---------------------------------------------------------------------------
__global__ void k_round(const float* __restrict__ wq, const float* __restrict__ wo) {
    const int NQ = 196608 / 4, NO = 65536 / 4;
    int i = blockIdx.x * blockDim.x + threadIdx.x;
    if (i < NQ + NO) {
        const float4* s;
        float4* d;
        if (i < NQ) { s = (const float4*)wq + i;        d = (float4*)g_wqkv + i; }
        else        { s = (const float4*)wo + (i - NQ); d = (float4*)g_wout + (i - NQ); }
        float4 v = __ldg(s);
        v.x = tf32f(v.x); v.y = tf32f(v.y); v.z = tf32f(v.z); v.w = tf32f(v.w);
        *d = v;
    }
}

// ---------------------------------------------------------------------------
// K1: qkv GEMM. CTA 128(M) x 128(N), K=256 in 8 chunks of 32.
// 3-stage ring: A via LDG(x)+cvt+STS, B via cp.async. One sync per chunk.
// 8 warps: 2(M,64) x 4(N,32). Epilogue scatters rounded q/k/v.
// ---------------------------------------------------------------------------
__global__ void __launch_bounds__(256, 2)
k_qkv(const float* __restrict__ x, const float* __restrict__ bqkv) {
    extern __shared__ float smf[];
    const int t = threadIdx.x;
    const int mbase = blockIdx.y << 7;
    const int nbase = blockIdx.x << 7;
    const int lane = t & 31, wid = t >> 5;
    const int g = lane >> 2, tg = lane & 3;
    const int wm = (wid & 1) << 6;
    const int wn = (wid >> 1) << 5;

    const uint32_t sbase = smem_u32(smf);
    const int srow = t >> 1, scol = (t & 1) << 4;
    const float* gA = x + (size_t)token_src(mbase + srow) * 256 + scol;
    const float* gB = g_wqkv + (size_t)(nbase + srow) * 256 + scol;
    const uint32_t offA = (srow * 36 + scol) * 4;   // byte offset within stage
    const uint32_t offB = offA + ABYTES;

    const int tt = lane >> 3, rr = lane & 7;
    const uint32_t aoff = (((tt & 1) * 8 + rr) * 36 + (tt >> 1) * 4) * 4;
    const uint32_t boff = (((tt >> 1) * 8 + rr) * 36 + (tt & 1) * 4) * 4;

    float acc[4][4][4] = {};

    // prologue: stages 0,1
#pragma unroll
    for (int s = 0; s < 2; ++s) {
#pragma unroll
        for (int j = 0; j < 4; ++j) {
            float4 v = __ldg((const float4*)(gA + s * 32 + j * 4));
            v.x = tf32f(v.x); v.y = tf32f(v.y); v.z = tf32f(v.z); v.w = tf32f(v.w);
            *(float4*)((char*)smf + s * STAGE + offA + j * 16) = v;
        }
#pragma unroll
        for (int j = 0; j < 4; ++j)
            cp16(sbase + s * STAGE + offB + j * 16, gB + s * 32 + j * 4);
        cp_commit();
    }

    for (int kc = 0; kc < 8; ++kc) {
        if (kc == 7) cp_wait<0>(); else cp_wait<1>();
        __syncthreads();

        if (kc < 6) {  // issue stage kc+2 (buffer (kc+2)%3 drained by barrier above)
            const int s = kc + 2;
            const uint32_t sb = (uint32_t)(s % 3) * STAGE;
#pragma unroll
            for (int j = 0; j < 4; ++j) {
                float4 v = __ldg((const float4*)(gA + s * 32 + j * 4));
                v.x = tf32f(v.x); v.y = tf32f(v.y); v.z = tf32f(v.z); v.w = tf32f(v.w);
                *(float4*)((char*)smf + sb + offA + j * 16) = v;
            }
#pragma unroll
            for (int j = 0; j < 4; ++j)
                cp16(sbase + sb + offB + j * 16, gB + s * 32 + j * 4);
            cp_commit();
        }

        const uint32_t base = sbase + (uint32_t)(kc % 3) * STAGE;
#pragma unroll
        for (int k8 = 0; k8 < 4; ++k8) {
            uint32_t af[4][4];
#pragma unroll
            for (int mt = 0; mt < 4; ++mt)
                ldsm4(af[mt], base + (wm + mt * 16) * 144 + aoff + k8 * 32);
            uint32_t bf[2][4];
#pragma unroll
            for (int bt = 0; bt < 2; ++bt)
                ldsm4(bf[bt], base + ABYTES + (wn + bt * 16) * 144 + boff + k8 * 32);
#pragma unroll
            for (int mt = 0; mt < 4; ++mt) {
                mma8(acc[mt][0], af[mt], bf[0][0], bf[0][1]);
                mma8(acc[mt][1], af[mt], bf[0][2], bf[0][3]);
                mma8(acc[mt][2], af[mt], bf[1][0], bf[1][1]);
                mma8(acc[mt][3], af[mt], bf[1][2], bf[1][3]);
            }
        }
    }

    const int which = nbase >> 8;  // uniform per CTA: 0=q, 1=k, 2=v
#pragma unroll
    for (int mt = 0; mt < 4; ++mt) {
#pragma unroll
        for (int half = 0; half < 2; ++half) {
            int m = mbase + wm + mt * 16 + g + half * 8;
            int w = m >> 6, p = m & 63;
#pragma unroll
            for (int nt = 0; nt < 4; ++nt) {
                int n0 = nbase + wn + nt * 8 + tg * 2;
                int h = (n0 >> 5) & 7, d = n0 & 31;
                int wh = (w << 3) + h;
                float v0 = tf32f(acc[mt][nt][half * 2 + 0] + __ldg(bqkv + n0));
                float v1 = tf32f(acc[mt][nt][half * 2 + 1] + __ldg(bqkv + n0 + 1));
                if (which == 0) {
                    *(float2*)(g_q + ((wh << 6) + p) * 32 + d) = make_float2(v0, v1);
                } else if (which == 1) {
                    *(float2*)(g_k + ((wh << 6) + p) * 32 + d) = make_float2(v0, v1);
                } else {
                    g_v[(((wh << 5) + d) << 6) + p] = v0;
                    g_v[(((wh << 5) + d + 1) << 6) + p] = v1;
                }
            }
        }
    }
}

// ---------------------------------------------------------------------------
// K2: attention per (window, head). 4 warps, each owns 16 full S rows.
// ---------------------------------------------------------------------------
__global__ void __launch_bounds__(128)
k_attn(const float* __restrict__ pos_enc) {
    __shared__ float qs[64 * 36];
    __shared__ float ks[64 * 36];
    __shared__ float vs[32 * 68];
    __shared__ float ps[64 * 68];
    __shared__ float pos_s[232];

    const int t = threadIdx.x;
    const int bh = blockIdx.x;
    const int w = bh >> 3, h = bh & 7;
    const int wh = (w << 3) + h;

    {
        int row = t >> 1, col = (t & 1) << 4;
        const float* q = g_q + ((size_t)(wh << 6) + row) * 32 + col;
        const float* k = g_k + ((size_t)(wh << 6) + row) * 32 + col;
        uint32_t dq = smem_u32(qs) + (row * 36 + col) * 4;
        uint32_t dk = smem_u32(ks) + (row * 36 + col) * 4;
#pragma unroll
        for (int j = 0; j < 4; ++j) { cp16(dq + j * 16, q + j * 4); cp16(dk + j * 16, k + j * 4); }
        int vr = t >> 2, vc = (t & 3) << 4;
        const float* v = g_v + ((size_t)(wh << 5) + vr) * 64 + vc;
        uint32_t dv = smem_u32(vs) + (vr * 68 + vc) * 4;
#pragma unroll
        for (int j = 0; j < 4; ++j) { cp16(dv + j * 16, v + j * 4); }
        cp_commit();
    }
    for (int i = t; i < 225; i += 128) pos_s[i] = __ldg(pos_enc + h * 225 + i);
    cp_wait<0>();
    __syncthreads();

    const int lane = t & 31, wid = t >> 5;
    const int g = lane >> 2, tg = lane & 3;
    const int wb = wid << 4;
    const int tt = lane >> 3, rr = lane & 7;
    const uint32_t aoff36 = (((tt & 1) * 8 + rr) * 36 + (tt >> 1) * 4) * 4;
    const uint32_t boff36 = (((tt >> 1) * 8 + rr) * 36 + (tt & 1) * 4) * 4;
    const uint32_t aoff68 = (((tt & 1) * 8 + rr) * 68 + (tt >> 1) * 4) * 4;
    const uint32_t boff68 = (((tt >> 1) * 8 + rr) * 68 + (tt & 1) * 4) * 4;

    // S = q k^T
    float sacc[8][4] = {};
    const uint32_t qb = smem_u32(qs) + wb * 144 + aoff36;
    const uint32_t kb = smem_u32(ks) + boff36;
#pragma unroll
    for (int k8 = 0; k8 < 4; ++k8) {
        uint32_t af[4];
        ldsm4(af, qb + k8 * 32);
        uint32_t bf[4][4];
#pragma unroll
        for (int bt = 0; bt < 4; ++bt)
            ldsm4(bf[bt], kb + bt * 16 * 144 + k8 * 32);
#pragma unroll
        for (int nt = 0; nt < 8; ++nt)
            mma8(sacc[nt], af, bf[nt >> 1][(nt & 1) * 2], bf[nt >> 1][(nt & 1) * 2 + 1]);
    }

    // bias + shift mask + softmax
    const int widx = w & 63;
    const int my = ((widx >> 3) == 7);
    const int mxw = ((widx & 7) == 7);
    auto regf = [&](int py, int px) {
        int ry = my ? (py < 4 ? 1 : 2) : 0;
        int rx = mxw ? (px < 4 ? 1 : 2) : 0;
        return ry * 3 + rx;
    };
    const int iL = wb + g, iH = iL + 8;
    const int pyL = iL >> 3, pxL = iL & 7;
    const int pyH = iH >> 3, pxH = iH & 7;
    const int regL = regf(pyL, pxL), regH = regf(pyH, pxH);

    float mL = -1e30f, mH = -1e30f;
#pragma unroll
    for (int nt = 0; nt < 8; ++nt) {
#pragma unroll
        for (int jj = 0; jj < 2; ++jj) {
            int j = (nt << 3) + (tg << 1) + jj;
            int pyj = j >> 3, pxj = j & 7;
            int regj = regf(pyj, pxj);
            float sL = sacc[nt][jj] * SCALE_F + pos_s[(pyL - pyj + 7) * 15 + (pxL - pxj + 7)];
            float sH = sacc[nt][2 + jj] * SCALE_F + pos_s[(pyH - pyj + 7) * 15 + (pxH - pxj + 7)];
            if (regj != regL) sL = -1e30f;
            if (regj != regH) sH = -1e30f;
            sacc[nt][jj] = sL;
            sacc[nt][2 + jj] = sH;
            mL = fmaxf(mL, sL);
            mH = fmaxf(mH, sH);
        }
    }
    mL = fmaxf(mL, __shfl_xor_sync(0xffffffffu, mL, 1));
    mL = fmaxf(mL, __shfl_xor_sync(0xffffffffu, mL, 2));
    mH = fmaxf(mH, __shfl_xor_sync(0xffffffffu, mH, 1));
    mH = fmaxf(mH, __shfl_xor_sync(0xffffffffu, mH, 2));

    float sumL = 0.f, sumH = 0.f;
#pragma unroll
    for (int nt = 0; nt < 8; ++nt) {
#pragma unroll
        for (int jj = 0; jj < 2; ++jj) {
            int j = (nt << 3) + (tg << 1) + jj;
            float eL = tf32f(__expf(sacc[nt][jj] - mL));
            float eH = tf32f(__expf(sacc[nt][2 + jj] - mH));
            sumL += eL;
            sumH += eH;
            ps[iL * 68 + j] = eL;
            ps[iH * 68 + j] = eH;
        }
    }
    sumL += __shfl_xor_sync(0xffffffffu, sumL, 1);
    sumL += __shfl_xor_sync(0xffffffffu, sumL, 2);
    sumH += __shfl_xor_sync(0xffffffffu, sumH, 1);
    sumH += __shfl_xor_sync(0xffffffffu, sumH, 2);
    const float invL = 1.f / sumL, invH = 1.f / sumH;
    __syncwarp();

    // O = P V
    float oacc[4][4] = {};
    const uint32_t pb = smem_u32(ps) + wb * 272 + aoff68;
    const uint32_t vb = smem_u32(vs) + boff68;
#pragma unroll
    for (int k8 = 0; k8 < 8; ++k8) {
        uint32_t pf[4];
        ldsm4(pf, pb + k8 * 32);
        uint32_t vf[2][4];
#pragma unroll
        for (int bt = 0; bt < 2; ++bt)
            ldsm4(vf[bt], vb + bt * 16 * 272 + k8 * 32);
#pragma unroll
        for (int nt = 0; nt < 4; ++nt)
            mma8(oacc[nt], pf, vf[nt >> 1][(nt & 1) * 2], vf[nt >> 1][(nt & 1) * 2 + 1]);
    }

    float* ob = g_o + (size_t)(w << 6) * 256 + (h << 5);
#pragma unroll
    for (int nt = 0; nt < 4; ++nt) {
        int d = (nt << 3) + (tg << 1);
        *(float2*)(ob + (size_t)iL * 256 + d) =
            make_float2(tf32f(oacc[nt][0] * invL), tf32f(oacc[nt][1] * invL));
        *(float2*)(ob + (size_t)iH * 256 + d) =
            make_float2(tf32f(oacc[nt][2] * invH), tf32f(oacc[nt][3] * invH));
    }
}

// ---------------------------------------------------------------------------
// K3: out = o @ w_out^T + b_out, 3-stage cp.async ring, inverse-roll scatter.
// ---------------------------------------------------------------------------
__global__ void __launch_bounds__(256, 2)
k_out(const float* __restrict__ bout, float* __restrict__ out) {
    extern __shared__ float smf[];
    const int t = threadIdx.x;
    const int mbase = blockIdx.y << 7;
    const int nbase = blockIdx.x << 7;
    const int lane = t & 31, wid = t >> 5;
    const int g = lane >> 2, tg = lane & 3;
    const int wm = (wid & 1) << 6;
    const int wn = (wid >> 1) << 5;

    const uint32_t sbase = smem_u32(smf);
    const int srow = t >> 1, scol = (t & 1) << 4;
    const float* gA = g_o + (size_t)(mbase + srow) * 256 + scol;
    const float* gB = g_wout + (size_t)(nbase + srow) * 256 + scol;
    const uint32_t offA = (srow * 36 + scol) * 4;
    const uint32_t offB = offA + ABYTES;

    const int tt = lane >> 3, rr = lane & 7;
    const uint32_t aoff = (((tt & 1) * 8 + rr) * 36 + (tt >> 1) * 4) * 4;
    const uint32_t boff = (((tt >> 1) * 8 + rr) * 36 + (tt & 1) * 4) * 4;

    float acc[4][4][4] = {};

#pragma unroll
    for (int s = 0; s < 2; ++s) {
        const uint32_t sb = sbase + s * STAGE;
#pragma unroll
        for (int j = 0; j < 4; ++j) {
            cp16(sb + offA + j * 16, gA + s * 32 + j * 4);
            cp16(sb + offB + j * 16, gB + s * 32 + j * 4);
        }
        cp_commit();
    }

    for (int kc = 0; kc < 8; ++kc) {
        if (kc == 7) cp_wait<0>(); else cp_wait<1>();
        __syncthreads();

        if (kc < 6) {
            const int s = kc + 2;
            const uint32_t sb = sbase + (uint32_t)(s % 3) * STAGE;
#pragma unroll
            for (int j = 0; j < 4; ++j) {
                cp16(sb + offA + j * 16, gA + s * 32 + j * 4);
                cp16(sb + offB + j * 16, gB + s * 32 + j * 4);
            }
            cp_commit();
        }

        const uint32_t base = sbase + (uint32_t)(kc % 3) * STAGE;
#pragma unroll
        for (int k8 = 0; k8 < 4; ++k8) {
            uint32_t af[4][4];
#pragma unroll
            for (int mt = 0; mt < 4; ++mt)
                ldsm4(af[mt], base + (wm + mt * 16) * 144 + aoff + k8 * 32);
            uint32_t bf[2][4];
#pragma unroll
            for (int bt = 0; bt < 2; ++bt)
                ldsm4(bf[bt], base + ABYTES + (wn + bt * 16) * 144 + boff + k8 * 32);
#pragma unroll
            for (int mt = 0; mt < 4; ++mt) {
                mma8(acc[mt][0], af[mt], bf[0][0], bf[0][1]);
                mma8(acc[mt][1], af[mt], bf[0][2], bf[0][3]);
                mma8(acc[mt][2], af[mt], bf[1][0], bf[1][1]);
                mma8(acc[mt][3], af[mt], bf[1][2], bf[1][3]);
            }
        }
    }

#pragma unroll
    for (int mt = 0; mt < 4; ++mt) {
#pragma unroll
        for (int half = 0; half < 2; ++half) {
            int m = mbase + wm + mt * 16 + g + half * 8;
            float* dst = out + (size_t)token_src(m) * 256;
#pragma unroll
            for (int nt = 0; nt < 4; ++nt) {
                int n0 = nbase + wn + nt * 8 + tg * 2;
                float2 val;
                val.x = acc[mt][nt][half * 2 + 0] + __ldg(bout + n0);
                val.y = acc[mt][nt][half * 2 + 1] + __ldg(bout + n0 + 1);
                *(float2*)(dst + n0) = val;
            }
        }
    }
}

// ---------------------------------------------------------------------------
extern "C" void kernel_launch(void* const* d_in, const int* in_sizes, int n_in,
                              void* d_out, int out_size) {
    const float* x    = (const float*)d_in[0];
    const float* wqkv = (const float*)d_in[1];
    const float* bqkv = (const float*)d_in[2];
    const float* wout = (const float*)d_in[3];
    const float* bout = (const float*)d_in[4];
    const float* pos  = (const float*)d_in[5];
    float* out = (float*)d_out;

    const int smem = 3 * STAGE;  // 110592
    cudaFuncSetAttribute(k_qkv, cudaFuncAttributeMaxDynamicSharedMemorySize, smem);
    cudaFuncSetAttribute(k_out, cudaFuncAttributeMaxDynamicSharedMemorySize, smem);

    k_round<<<256, 256>>>(wqkv, wout);
    k_qkv<<<dim3(6, 1024), 256, smem>>>(x, bqkv);
    k_attn<<<16384, 128>>>(pos);
    k_out<<<dim3(2, 1024), 256, smem>>>(bout, out);
}